// round 6
// baseline (speedup 1.0000x reference)
#include <cuda_runtime.h>
#include <math.h>

#define Bq 8
#define Cc 64
#define Hh 28
#define Ww 28
#define Ll 784
#define HIDd 128
#define Sdim 64
#define NHh 16
#define HDd 4
#define DIMc 256

// ---------------- scratch (static device globals; no allocation) ----------------
__device__ float g_x1o [Bq*Cc*Ll];
__device__ float g_x1g [Bq*Cc*Ll];
__device__ float g_b1  [Bq*Cc*Ll];
__device__ float g_mp  [Bq*Cc*Ll];
__device__ float g_b2  [Bq*Cc*Ll];
__device__ float g_bcdt1[Bq*192*Ll];
__device__ float g_bcdt2[Bq*192*Ll];
__device__ float g_wsl [Bq*Sdim*Ll];
__device__ float g_h   [Bq*Cc*Sdim];
__device__ float g_h2  [Bq*Cc*Sdim];
__device__ float g_b3  [Bq*Cc*Ll];
__device__ float g_qb  [Bq*NHh*Ll*HDd];
__device__ float g_kb  [Bq*NHh*Ll*HDd];
__device__ float g_vb  [Bq*NHh*Ll*HDd];
__device__ float g_ob  [Bq*Ll*Cc];
__device__ float g_b4  [Bq*Cc*Ll];
__device__ float g_m1  [Bq*HIDd*Ll];

__device__ __forceinline__ float bnf(float x, const float* __restrict__ p, int c, int C){
    return (x - p[2*C+c]) * p[c] * rsqrtf(p[3*C+c] + 1e-5f) + p[C+c];
}

// ---------------- branch 1 ----------------
// dw1: depthwise 7x7 pad3 + bias + BN.  Reads x (quarter 0), writes g_x1o.
// NOTE: device globals are referenced INSIDE device code only (never passed
// from host — the host-side shadow address is not the device address).
__global__ void k_dw7a(const float* __restrict__ x, const float* __restrict__ w,
                       const float* __restrict__ bias, const float* __restrict__ bnp){
    int idx = blockIdx.x*256 + threadIdx.x;
    if (idx >= Bq*Cc*Ll) return;
    int p = idx % Ll; int c = (idx/Ll) % Cc; int b = idx/(Ll*Cc);
    int y = p/Ww, xx = p%Ww;
    const float* ip = x + ((size_t)(b*DIMc + 0 + c))*Ll;
    const float* wc = w + c*49;
    float acc = bias[c];
    #pragma unroll
    for (int ky=0; ky<7; ky++){
        int yy = y+ky-3; if ((unsigned)yy >= 28u) continue;
        #pragma unroll
        for (int kx=0; kx<7; kx++){
            int xw = xx+kx-3; if ((unsigned)xw >= 28u) continue;
            acc += wc[ky*7+kx] * ip[yy*28+xw];
        }
    }
    g_x1o[idx] = bnf(acc, bnp, c, Cc);
}

// dw2: depthwise 7x7 pad3 + bias (no BN).  Reads g_x1g, writes g_b1.
__global__ void k_dw7b(const float* __restrict__ w, const float* __restrict__ bias){
    int idx = blockIdx.x*256 + threadIdx.x;
    if (idx >= Bq*Cc*Ll) return;
    int p = idx % Ll; int c = (idx/Ll) % Cc; int b = idx/(Ll*Cc);
    int y = p/Ww, xx = p%Ww;
    const float* ip = g_x1g + ((size_t)(b*Cc + c))*Ll;
    const float* wc = w + c*49;
    float acc = bias[c];
    #pragma unroll
    for (int ky=0; ky<7; ky++){
        int yy = y+ky-3; if ((unsigned)yy >= 28u) continue;
        #pragma unroll
        for (int kx=0; kx<7; kx++){
            int xw = xx+kx-3; if ((unsigned)xw >= 28u) continue;
            acc += wc[ky*7+kx] * ip[yy*28+xw];
        }
    }
    g_b1[idx] = acc;
}

__global__ void k_star(const float* __restrict__ f1w, const float* __restrict__ f1b,
                       const float* __restrict__ f2w, const float* __restrict__ f2b,
                       const float* __restrict__ gw,  const float* __restrict__ gb,
                       const float* __restrict__ bng){
    __shared__ float xv[64], ts[128];
    int bl = blockIdx.x; int b = bl/Ll, p = bl%Ll;
    int tid = threadIdx.x;
    if (tid < 64) xv[tid] = g_x1o[((size_t)b*64 + tid)*Ll + p];
    __syncthreads();
    float a1 = f1b[tid], a2 = f2b[tid];
    const float* w1 = f1w + tid*64; const float* w2 = f2w + tid*64;
    #pragma unroll 8
    for (int c=0;c<64;c++){ float xc = xv[c]; a1 += w1[c]*xc; a2 += w2[c]*xc; }
    a1 = fminf(fmaxf(a1, 0.f), 6.f);
    ts[tid] = a1*a2;
    __syncthreads();
    if (tid < 64){
        float acc = gb[tid];
        const float* wg = gw + tid*128;
        #pragma unroll 8
        for (int j=0;j<128;j++) acc += wg[j]*ts[j];
        g_x1g[((size_t)b*64 + tid)*Ll + p] = bnf(acc, bng, tid, 64);
    }
}

// ---------------- branch 2 ----------------
__global__ void k_max(const float* __restrict__ x){
    int idx = blockIdx.x*256 + threadIdx.x;
    if (idx >= Bq*Cc*Ll) return;
    int p = idx % Ll, c = (idx/Ll)%Cc, b = idx/(Ll*Cc);
    int y = p/28, xx = p%28;
    const float* ip = x + ((size_t)(b*DIMc + 64 + c))*Ll;
    float m = -1e30f;
    #pragma unroll
    for (int dy=-1; dy<=1; dy++){ int yy=y+dy; if ((unsigned)yy>=28u) continue;
        #pragma unroll
        for (int dx=-1; dx<=1; dx++){ int xw=xx+dx; if ((unsigned)xw>=28u) continue;
            m = fmaxf(m, ip[yy*28+xw]); } }
    g_mp[idx] = m;
}

__global__ void k_att(const float* __restrict__ x,
                      const float* __restrict__ wh1, const float* __restrict__ wv1,
                      const float* __restrict__ wh2, const float* __restrict__ wv2,
                      const float* __restrict__ bnm){
    __shared__ float xt[100], sacc[100], sh[190], cbuf[190];
    __shared__ float sw1[33], sw2[33], sw3[33], sw4[33];
    int bc = blockIdx.x; int b = bc/64, c = bc%64;
    int tid = threadIdx.x;
    if (tid < 33){ sw1[tid]=wh1[c*33+tid]; sw2[tid]=wv1[c*33+tid];
                   sw3[tid]=wh2[c*33+tid]; sw4[tid]=wv2[c*33+tid]; }
    const float* mpc = g_mp + (size_t)bc*Ll;
    if (tid < 100){
        int oy = tid/10, ox = tid%10;
        const float fa[4] = {1.f,3.f,3.f,1.f};
        float acc = 0.f;
        #pragma unroll
        for (int ty=0; ty<4; ty++){
            int q = 3*oy + ty - 1; if (q < 0) q = -q; if (q >= 28) q = 54 - q;
            #pragma unroll
            for (int tx=0; tx<4; tx++){
                int r = 3*ox + tx - 1; if (r < 0) r = -r; if (r >= 28) r = 54 - r;
                acc += fa[ty]*fa[tx]*mpc[q*28+r];
            }
        }
        xt[tid] = acc * (1.0f/64.0f);
    }
    __syncthreads();
    if (tid < 100){
        int y = tid/10, xo = tid%10;
        float s = 0.f;
        #pragma unroll
        for (int ky=0; ky<11; ky++){ int yy=y+ky-5; if ((unsigned)yy>=10u) continue;
            #pragma unroll
            for (int kx=0; kx<3; kx++){ int xx=xo+kx-1; if ((unsigned)xx>=10u) continue;
                s += sw1[ky*3+kx]*xt[yy*10+xx]; } }
        #pragma unroll
        for (int ky=0; ky<3; ky++){ int yy=y+ky-1; if ((unsigned)yy>=10u) continue;
            #pragma unroll
            for (int kx=0; kx<11; kx++){ int xx=xo+kx-5; if ((unsigned)xx>=10u) continue;
                s += sw2[ky*11+kx]*xt[yy*10+xx]; } }
        sacc[tid] = s;
    }
    if (tid < 190){
        int r = tid/19, j = tid%19, d = j - r;
        sh[tid] = (d >= 0 && d < 10) ? xt[r*10 + d] : 0.f;
    }
    __syncthreads();
    if (tid < 190){
        int u = tid/19, v = tid%19;
        float s = 0.f;
        #pragma unroll
        for (int ky=0; ky<11; ky++){ int uu=u+ky-5; if ((unsigned)uu>=10u) continue;
            #pragma unroll
            for (int kx=0; kx<3; kx++){ int vv=v+kx-1; if ((unsigned)vv>=19u) continue;
                s += sw3[ky*3+kx]*sh[uu*19+vv]; } }
        cbuf[tid] = s;
    }
    __syncthreads();
    if (tid < 100){
        int y = tid/10, xo = tid%10;
        int g = 20*y + xo;
        sacc[tid] += cbuf[g];
    }
    __syncthreads();
    if (tid < 190){
        int a = tid/10, b2 = tid%10, d = a - b2;
        sh[tid] = (d >= 0 && d < 10) ? xt[d*10 + b2] : 0.f;
    }
    __syncthreads();
    if (tid < 190){
        int a = tid/10, b2 = tid%10;
        float s = 0.f;
        #pragma unroll
        for (int ky=0; ky<3; ky++){ int av=a+ky-1; if ((unsigned)av>=19u) continue;
            #pragma unroll
            for (int kx=0; kx<11; kx++){ int bv=b2+kx-5; if ((unsigned)bv>=10u) continue;
                s += sw4[ky*11+kx]*sh[av*10+bv]; } }
        cbuf[tid] = s;
    }
    __syncthreads();
    if (tid < 100){
        int y = tid/10, xo = tid%10;
        int g = 20*xo + y;
        float s = sacc[tid] + cbuf[(g%19)*10 + (g/19)];
        s = bnf(s, bnm, c, 64);
        sacc[tid] = 1.f/(1.f + __expf(-s));
    }
    __syncthreads();
    const float* x2 = x + ((size_t)(b*DIMc + 64 + c))*Ll;
    float* op = g_b2 + (size_t)bc*Ll;
    for (int p=tid; p<Ll; p+=blockDim.x){
        int y = p/28, xx = p%28;
        op[p] = x2[p] * sacc[(y*10/28)*10 + (xx*10/28)];
    }
}

// ---------------- branch 3 (HSMSSD) ----------------
__global__ void k_bcdt(const float* __restrict__ x, const float* __restrict__ w){
    __shared__ float xv[64];
    int bl = blockIdx.x; int b = bl/Ll, p = bl%Ll;
    int tid = threadIdx.x;
    if (tid < 64) xv[tid] = x[((size_t)(b*DIMc + 128 + tid))*Ll + p];
    __syncthreads();
    float acc = 0.f; const float* wr = w + tid*64;
    #pragma unroll 8
    for (int c=0;c<64;c++) acc += wr[c]*xv[c];
    g_bcdt1[((size_t)b*192 + tid)*Ll + p] = acc;
}

__global__ void k_dw3(const float* __restrict__ w){
    int idx = blockIdx.x*256 + threadIdx.x;
    if (idx >= Bq*192*Ll) return;
    int p = idx%Ll, c = (idx/Ll)%192, b = idx/(Ll*192);
    int y = p/28, x = p%28;
    const float* ip = g_bcdt1 + ((size_t)b*192 + c)*Ll;
    const float* wc = w + c*9;
    float acc = 0.f;
    #pragma unroll
    for (int ky=0; ky<3; ky++){ int yy=y+ky-1; if ((unsigned)yy>=28u) continue;
        #pragma unroll
        for (int kx=0; kx<3; kx++){ int xx=x+kx-1; if ((unsigned)xx>=28u) continue;
            acc += wc[ky*3+kx]*ip[yy*28+xx]; } }
    g_bcdt2[idx] = acc;
}

__global__ void k_softAB(const float* __restrict__ Ap){
    __shared__ float red[256];
    int bs = blockIdx.x; int b = bs/64, s = bs%64;
    int tid = threadIdx.x;
    const float av = Ap[s];
    const float* dt = g_bcdt2 + ((size_t)b*192 + 128 + s)*Ll;
    const float* Bm = g_bcdt2 + ((size_t)b*192 + s)*Ll;
    float m = -1e30f;
    for (int l=tid; l<Ll; l+=256) m = fmaxf(m, dt[l] + av);
    red[tid] = m; __syncthreads();
    for (int o=128; o>0; o>>=1){ if (tid<o) red[tid]=fmaxf(red[tid],red[tid+o]); __syncthreads(); }
    m = red[0]; __syncthreads();
    float sum = 0.f;
    for (int l=tid; l<Ll; l+=256) sum += __expf(dt[l] + av - m);
    red[tid] = sum; __syncthreads();
    for (int o=128; o>0; o>>=1){ if (tid<o) red[tid]+=red[tid+o]; __syncthreads(); }
    float inv = 1.f/red[0];
    float* wo = g_wsl + ((size_t)b*64 + s)*Ll;
    for (int l=tid; l<Ll; l+=256) wo[l] = __expf(dt[l] + av - m)*inv*Bm[l];
}

__global__ void k_h(const float* __restrict__ x){
    __shared__ float wr[Ll];
    int bs = blockIdx.x; int b = bs/64, s = bs%64;
    int tid = threadIdx.x;
    const float* wp = g_wsl + ((size_t)b*64 + s)*Ll;
    for (int l=tid; l<Ll; l+=64) wr[l] = wp[l];
    __syncthreads();
    const float* xs = x + ((size_t)(b*DIMc + 128 + tid))*Ll;
    float acc = 0.f;
    #pragma unroll 4
    for (int l=0; l<Ll; l++) acc += xs[l]*wr[l];
    g_h[((size_t)b*64 + tid)*64 + s] = acc;
}

__global__ void k_hz(const float* __restrict__ hzw, const float* __restrict__ outw,
                     const float* __restrict__ Dp){
    __shared__ float hc[64], hzv[128], gs[64];
    int bs = blockIdx.x; int b = bs/64, s = bs%64;
    int tid = threadIdx.x;
    if (tid < 64) hc[tid] = g_h[((size_t)b*64 + tid)*64 + s];
    __syncthreads();
    float acc = 0.f; const float* wr = hzw + tid*64;
    #pragma unroll 8
    for (int c=0;c<64;c++) acc += wr[c]*hc[c];
    hzv[tid] = acc;
    __syncthreads();
    if (tid < 64){
        float hv = hzv[tid], z = hzv[64+tid];
        gs[tid] = hv * (z/(1.f+__expf(-z))) + hv*Dp[0];
    }
    __syncthreads();
    if (tid < 64){
        float a2 = 0.f; const float* wo = outw + tid*64;
        #pragma unroll 8
        for (int c=0;c<64;c++) a2 += wo[c]*gs[c];
        g_h2[((size_t)b*64 + tid)*64 + s] = a2;
    }
}

__global__ void k_x3(){
    __shared__ float cs[64*112];
    int b = blockIdx.x; int l0 = blockIdx.y*112;
    int tid = threadIdx.x;
    for (int i=tid; i<64*112; i+=256){
        int s = i/112, lo = i%112;
        cs[i] = g_bcdt2[((size_t)b*192 + 64 + s)*Ll + l0 + lo];
    }
    __syncthreads();
    for (int i=tid; i<64*112; i+=256){
        int c = i/112, lo = i%112;
        const float* hr = g_h2 + ((size_t)b*64 + c)*64;
        float acc = 0.f;
        #pragma unroll 8
        for (int s=0; s<64; s++) acc += hr[s]*cs[s*112+lo];
        g_b3[((size_t)b*64 + c)*Ll + l0 + lo] = acc;
    }
}

// ---------------- branch 4 (GA attention) ----------------
__global__ void k_qkv(const float* __restrict__ x, const float* __restrict__ w){
    __shared__ float xv[64];
    int bn = blockIdx.x; int b = bn/Ll, n = bn%Ll;
    int tid = threadIdx.x;
    if (tid < 64) xv[tid] = x[((size_t)(b*DIMc + 192 + tid))*Ll + n];
    __syncthreads();
    float acc = 0.f; const float* wr = w + tid*64;
    #pragma unroll 8
    for (int c=0;c<64;c++) acc += wr[c]*xv[c];
    int part = tid/64, rem = tid%64; int hh = rem/4, dd = rem%4;
    float* dst = (part==0) ? g_qb : (part==1) ? g_kb : g_vb;
    dst[(((size_t)b*16 + hh)*Ll + n)*4 + dd] = acc;
}

__global__ void k_attn(){
    __shared__ float Ks[Ll*4], Vs[Ll*4];
    int bh = blockIdx.x;
    size_t base = (size_t)bh * Ll * 4;
    int tid = threadIdx.x;
    for (int i=tid; i<Ll*4; i+=Ll){ Ks[i] = g_kb[base+i]; Vs[i] = g_vb[base+i]; }
    __syncthreads();
    float q0 = g_qb[base + tid*4 + 0];
    float q1 = g_qb[base + tid*4 + 1];
    float q2 = g_qb[base + tid*4 + 2];
    float q3 = g_qb[base + tid*4 + 3];
    float mx = -1e30f;
    for (int j=0; j<Ll; j++){
        float s = 0.5f*(q0*Ks[j*4] + q1*Ks[j*4+1] + q2*Ks[j*4+2] + q3*Ks[j*4+3]);
        mx = fmaxf(mx, s);
    }
    float den = 0.f, a0 = 0.f, a1 = 0.f, a2 = 0.f, a3 = 0.f;
    for (int j=0; j<Ll; j++){
        float s = 0.5f*(q0*Ks[j*4] + q1*Ks[j*4+1] + q2*Ks[j*4+2] + q3*Ks[j*4+3]);
        float e = __expf(s - mx);
        den += e;
        a0 += e*Vs[j*4]; a1 += e*Vs[j*4+1]; a2 += e*Vs[j*4+2]; a3 += e*Vs[j*4+3];
    }
    float inv = 1.f/den;
    int b = bh/16, hh = bh%16;
    float* op = g_ob + ((size_t)b*Ll + tid)*64 + hh*4;
    op[0] = a0*inv; op[1] = a1*inv; op[2] = a2*inv; op[3] = a3*inv;
}

__global__ void k_proj(const float* __restrict__ x, const float* __restrict__ pw,
                       const float* __restrict__ bnp){
    __shared__ float ov[64];
    int bn = blockIdx.x; int b = bn/Ll, n = bn%Ll;
    int tid = threadIdx.x;
    ov[tid] = g_ob[((size_t)b*Ll + n)*64 + tid];
    __syncthreads();
    float acc = 0.f; const float* wr = pw + tid*64;
    #pragma unroll 8
    for (int j=0;j<64;j++) acc += wr[j]*ov[j];
    float xv = x[((size_t)(b*DIMc + 192 + tid))*Ll + n];
    g_b4[((size_t)b*64 + tid)*Ll + n] = bnf(xv + acc, bnp, tid, 64);
}

// ---------------- merge MLP ----------------
__global__ void k_mlp1(const float* __restrict__ w, const float* __restrict__ bnp){
    __shared__ float xa[256];
    int bl = blockIdx.x; int b = bl/Ll, p = bl%Ll;
    int tid = threadIdx.x;
    for (int i=tid; i<256; i+=128){
        const float* src = (i<64) ? g_b1 : (i<128) ? g_b2 : (i<192) ? g_b3 : g_b4;
        xa[i] = src[((size_t)b*64 + (i&63))*Ll + p];
    }
    __syncthreads();
    float acc = 0.f; const float* wr = w + tid*256;
    #pragma unroll 8
    for (int c=0;c<256;c++) acc += wr[c]*xa[c];
    acc = bnf(acc, bnp, tid, 128);
    g_m1[((size_t)b*HIDd + tid)*Ll + p] = fmaxf(acc, 0.f);
}

__global__ void k_mlp2(const float* __restrict__ x, const float* __restrict__ w,
                       const float* __restrict__ bnp, float* __restrict__ out){
    __shared__ float mv[128];
    int bl = blockIdx.x; int b = bl/Ll, p = bl%Ll;
    int tid = threadIdx.x;
    if (tid < 128) mv[tid] = g_m1[((size_t)b*HIDd + tid)*Ll + p];
    __syncthreads();
    float acc = 0.f; const float* wr = w + tid*128;
    #pragma unroll 8
    for (int j=0;j<128;j++) acc += wr[j]*mv[j];
    size_t idx = ((size_t)(b*DIMc + tid))*Ll + p;
    out[idx] = x[idx] + bnf(acc, bnp, tid, 256);
}

// ---------------- launch ----------------
extern "C" void kernel_launch(void* const* d_in, const int* in_sizes, int n_in,
                              void* d_out, int out_size){
    const float* x       = (const float*)d_in[0];
    const float* dw1_w   = (const float*)d_in[1];
    const float* dw1_b   = (const float*)d_in[2];
    const float* bn_dw1  = (const float*)d_in[3];
    const float* f1_w    = (const float*)d_in[4];
    const float* f1_b    = (const float*)d_in[5];
    const float* f2_w    = (const float*)d_in[6];
    const float* f2_b    = (const float*)d_in[7];
    const float* g_w     = (const float*)d_in[8];
    const float* g_b     = (const float*)d_in[9];
    const float* bn_g    = (const float*)d_in[10];
    const float* dw2_w   = (const float*)d_in[11];
    const float* dw2_b   = (const float*)d_in[12];
    const float* hatt1_w = (const float*)d_in[13];
    const float* vatt1_w = (const float*)d_in[14];
    const float* hatt2_w = (const float*)d_in[15];
    const float* vatt2_w = (const float*)d_in[16];
    const float* bn_mra  = (const float*)d_in[17];
    const float* bcdt_w  = (const float*)d_in[18];
    const float* ssd_dw_w= (const float*)d_in[19];
    const float* hz_w    = (const float*)d_in[20];
    const float* out_w   = (const float*)d_in[21];
    const float* A_param = (const float*)d_in[22];
    const float* D_param = (const float*)d_in[23];
    const float* qkv_w   = (const float*)d_in[24];
    const float* proj_w  = (const float*)d_in[25];
    const float* bn_n4   = (const float*)d_in[26];
    const float* mlp1_w  = (const float*)d_in[27];
    const float* bn_mlp  = (const float*)d_in[28];
    const float* mlp2_w  = (const float*)d_in[29];
    const float* bn_n1   = (const float*)d_in[30];
    float* out = (float*)d_out;
    (void)n_in; (void)in_sizes; (void)out_size;

    const int NE  = Bq*Cc*Ll;       // 401408
    const int NE3 = Bq*192*Ll;      // 1204224
    const int NP  = Bq*Ll;          // 6272

    // branch 1
    k_dw7a<<<(NE+255)/256, 256>>>(x, dw1_w, dw1_b, bn_dw1);
    k_star<<<NP, 128>>>(f1_w, f1_b, f2_w, f2_b, g_w, g_b, bn_g);
    k_dw7b<<<(NE+255)/256, 256>>>(dw2_w, dw2_b);

    // branch 2
    k_max<<<(NE+255)/256, 256>>>(x);
    k_att<<<Bq*Cc, 256>>>(x, hatt1_w, vatt1_w, hatt2_w, vatt2_w, bn_mra);

    // branch 3
    k_bcdt<<<NP, 192>>>(x, bcdt_w);
    k_dw3<<<(NE3+255)/256, 256>>>(ssd_dw_w);
    k_softAB<<<Bq*Sdim, 256>>>(A_param);
    k_h<<<Bq*Sdim, 64>>>(x);
    k_hz<<<Bq*Sdim, 128>>>(hz_w, out_w, D_param);
    k_x3<<<dim3(Bq, 7), 256>>>();

    // branch 4
    k_qkv<<<NP, 192>>>(x, qkv_w);
    k_attn<<<Bq*NHh, Ll>>>();
    k_proj<<<NP, 64>>>(x, proj_w, bn_n4);

    // merge MLP
    k_mlp1<<<NP, 128>>>(mlp1_w, bn_mlp);
    k_mlp2<<<NP, 256>>>(x, mlp2_w, bn_n1, out);
}

// round 7
// speedup vs baseline: 6.1348x; 6.1348x over previous
#include <cuda_runtime.h>
#include <math.h>

#define Bq 8
#define Cc 64
#define Ll 784
#define HIDd 128
#define Sdim 64
#define NHh 16
#define DIMc 256
#define PT 49           // pixels per tile
#define NTt 16          // tiles (16*49 = 784)

// ---------------- scratch ----------------
__device__ float g_x1o [Bq*Cc*Ll];
__device__ float g_x1g [Bq*Cc*Ll];
__device__ float g_b1  [Bq*Cc*Ll];
__device__ float g_b2  [Bq*Cc*Ll];
__device__ float g_bcdt1[Bq*192*Ll];
__device__ float g_bcdt2[Bq*192*Ll];
__device__ float g_wsl [Bq*Sdim*Ll];
__device__ float g_h   [Bq*Cc*Sdim];
__device__ float g_h2  [Bq*Cc*Sdim];
__device__ float g_b3  [Bq*Cc*Ll];
__device__ float g_qb  [Bq*NHh*Ll*4];
__device__ float g_kb  [Bq*NHh*Ll*4];
__device__ float g_vb  [Bq*NHh*Ll*4];
__device__ float g_ob  [Bq*Ll*Cc];
__device__ float g_b4  [Bq*Cc*Ll];
__device__ float g_m1  [Bq*HIDd*Ll];

__device__ __forceinline__ float bnf(float x, const float* __restrict__ p, int c, int C){
    return (x - p[2*C+c]) * p[c] * rsqrtf(p[3*C+c] + 1e-5f) + p[C+c];
}

// ---------------- branch 1 ----------------
__global__ void k_dw7a(const float* __restrict__ x, const float* __restrict__ w,
                       const float* __restrict__ bias, const float* __restrict__ bnp){
    int idx = blockIdx.x*256 + threadIdx.x;
    if (idx >= Bq*Cc*Ll) return;
    int p = idx % Ll; int c = (idx/Ll) % Cc; int b = idx/(Ll*Cc);
    int y = p/28, xx = p%28;
    const float* ip = x + ((size_t)(b*DIMc + c))*Ll;
    const float* wc = w + c*49;
    float acc = bias[c];
    #pragma unroll
    for (int ky=0; ky<7; ky++){
        int yy = y+ky-3; if ((unsigned)yy >= 28u) continue;
        #pragma unroll
        for (int kx=0; kx<7; kx++){
            int xw = xx+kx-3; if ((unsigned)xw >= 28u) continue;
            acc += wc[ky*7+kx] * ip[yy*28+xw];
        }
    }
    g_x1o[idx] = bnf(acc, bnp, c, Cc);
}

__global__ void k_dw7b(const float* __restrict__ w, const float* __restrict__ bias){
    int idx = blockIdx.x*256 + threadIdx.x;
    if (idx >= Bq*Cc*Ll) return;
    int p = idx % Ll; int c = (idx/Ll) % Cc; int b = idx/(Ll*Cc);
    int y = p/28, xx = p%28;
    const float* ip = g_x1g + ((size_t)(b*Cc + c))*Ll;
    const float* wc = w + c*49;
    float acc = bias[c];
    #pragma unroll
    for (int ky=0; ky<7; ky++){
        int yy = y+ky-3; if ((unsigned)yy >= 28u) continue;
        #pragma unroll
        for (int kx=0; kx<7; kx++){
            int xw = xx+kx-3; if ((unsigned)xw >= 28u) continue;
            acc += wc[ky*7+kx] * ip[yy*28+xw];
        }
    }
    g_b1[idx] = acc;
}

// star MLP, weight-stationary tile: block per (b, 49-px tile)
__global__ void __launch_bounds__(256,1)
k_star_t(const float* __restrict__ f1w, const float* __restrict__ f1b,
         const float* __restrict__ f2w, const float* __restrict__ f2b,
         const float* __restrict__ gw,  const float* __restrict__ gb,
         const float* __restrict__ bng){
    extern __shared__ float sm[];
    float* sf1 = sm;                 // 8192
    float* sf2 = sf1 + 8192;         // 8192
    float* sg  = sf2 + 8192;         // 8192
    float* sb1 = sg  + 8192;         // 128
    float* sb2 = sb1 + 128;          // 128
    float* sgb = sb2 + 128;          // 64
    float* sbn = sgb + 64;           // 256
    float* sxv = sbn + 256;          // 64*49
    float* sts = sxv + 64*PT;        // 128*49
    int b = blockIdx.x / NTt, p0 = (blockIdx.x % NTt) * PT;
    int tid = threadIdx.x;
    for (int i=tid; i<8192; i+=256){ sf1[i]=f1w[i]; sf2[i]=f2w[i]; sg[i]=gw[i]; }
    if (tid<128){ sb1[tid]=f1b[tid]; sb2[tid]=f2b[tid]; }
    if (tid<64) sgb[tid]=gb[tid];
    sbn[tid] = bng[tid];
    for (int i=tid; i<64*PT; i+=256){
        int c=i/PT, px=i%PT;
        sxv[i] = g_x1o[((size_t)(b*64+c))*Ll + p0+px];
    }
    __syncthreads();
    for (int i=tid; i<128*PT; i+=256){
        int h=i/PT, px=i%PT;
        float a1=sb1[h], a2=sb2[h];
        const float* w1=sf1+h*64; const float* w2=sf2+h*64;
        #pragma unroll 8
        for (int c=0;c<64;c++){ float xc=sxv[c*PT+px]; a1+=w1[c]*xc; a2+=w2[c]*xc; }
        a1 = fminf(fmaxf(a1,0.f),6.f);
        sts[i] = a1*a2;
    }
    __syncthreads();
    for (int i=tid; i<64*PT; i+=256){
        int o=i/PT, px=i%PT;
        float acc=sgb[o];
        const float* wg=sg+o*128;
        #pragma unroll 8
        for (int j=0;j<128;j++) acc += wg[j]*sts[j*PT+px];
        g_x1g[((size_t)(b*64+o))*Ll + p0+px] = bnf(acc, sbn, o, 64);
    }
}

// ---------------- branch 2: maxpool fused ----------------
__global__ void k_att2(const float* __restrict__ x,
                       const float* __restrict__ wh1, const float* __restrict__ wv1,
                       const float* __restrict__ wh2, const float* __restrict__ wv2,
                       const float* __restrict__ bnm){
    __shared__ float mp[784], xt[100], sacc[100], sh[190], cbuf[190];
    __shared__ float sw1[33], sw2[33], sw3[33], sw4[33];
    int bc = blockIdx.x; int b = bc/64, c = bc%64;
    int tid = threadIdx.x;
    if (tid < 33){ sw1[tid]=wh1[c*33+tid]; sw2[tid]=wv1[c*33+tid];
                   sw3[tid]=wh2[c*33+tid]; sw4[tid]=wv2[c*33+tid]; }
    const float* x2 = x + ((size_t)(b*DIMc + 64 + c))*Ll;
    // maxpool 3x3 into smem
    for (int p=tid; p<784; p+=256){
        int y=p/28, xx=p%28;
        float m = -1e30f;
        #pragma unroll
        for (int dy=-1; dy<=1; dy++){ int yy=y+dy; if ((unsigned)yy>=28u) continue;
            #pragma unroll
            for (int dx=-1; dx<=1; dx++){ int xw=xx+dx; if ((unsigned)xw>=28u) continue;
                m = fmaxf(m, x2[yy*28+xw]); } }
        mp[p] = m;
    }
    __syncthreads();
    if (tid < 100){
        int oy = tid/10, ox = tid%10;
        const float fa[4] = {1.f,3.f,3.f,1.f};
        float acc = 0.f;
        #pragma unroll
        for (int ty=0; ty<4; ty++){
            int q = 3*oy + ty - 1; if (q < 0) q = -q; if (q >= 28) q = 54 - q;
            #pragma unroll
            for (int tx=0; tx<4; tx++){
                int r = 3*ox + tx - 1; if (r < 0) r = -r; if (r >= 28) r = 54 - r;
                acc += fa[ty]*fa[tx]*mp[q*28+r];
            }
        }
        xt[tid] = acc * (1.0f/64.0f);
    }
    __syncthreads();
    if (tid < 100){
        int y = tid/10, xo = tid%10;
        float s = 0.f;
        #pragma unroll
        for (int ky=0; ky<11; ky++){ int yy=y+ky-5; if ((unsigned)yy>=10u) continue;
            #pragma unroll
            for (int kx=0; kx<3; kx++){ int xx=xo+kx-1; if ((unsigned)xx>=10u) continue;
                s += sw1[ky*3+kx]*xt[yy*10+xx]; } }
        #pragma unroll
        for (int ky=0; ky<3; ky++){ int yy=y+ky-1; if ((unsigned)yy>=10u) continue;
            #pragma unroll
            for (int kx=0; kx<11; kx++){ int xx=xo+kx-5; if ((unsigned)xx>=10u) continue;
                s += sw2[ky*11+kx]*xt[yy*10+xx]; } }
        sacc[tid] = s;
    }
    if (tid < 190){
        int r = tid/19, j = tid%19, d = j - r;
        sh[tid] = (d >= 0 && d < 10) ? xt[r*10 + d] : 0.f;
    }
    __syncthreads();
    if (tid < 190){
        int u = tid/19, v = tid%19;
        float s = 0.f;
        #pragma unroll
        for (int ky=0; ky<11; ky++){ int uu=u+ky-5; if ((unsigned)uu>=10u) continue;
            #pragma unroll
            for (int kx=0; kx<3; kx++){ int vv=v+kx-1; if ((unsigned)vv>=19u) continue;
                s += sw3[ky*3+kx]*sh[uu*19+vv]; } }
        cbuf[tid] = s;
    }
    __syncthreads();
    if (tid < 100){
        int y = tid/10, xo = tid%10;
        sacc[tid] += cbuf[20*y + xo];
    }
    __syncthreads();
    if (tid < 190){
        int a = tid/10, b2 = tid%10, d = a - b2;
        sh[tid] = (d >= 0 && d < 10) ? xt[d*10 + b2] : 0.f;
    }
    __syncthreads();
    if (tid < 190){
        int a = tid/10, b2 = tid%10;
        float s = 0.f;
        #pragma unroll
        for (int ky=0; ky<3; ky++){ int av=a+ky-1; if ((unsigned)av>=19u) continue;
            #pragma unroll
            for (int kx=0; kx<11; kx++){ int bv=b2+kx-5; if ((unsigned)bv>=10u) continue;
                s += sw4[ky*11+kx]*sh[av*10+bv]; } }
        cbuf[tid] = s;
    }
    __syncthreads();
    if (tid < 100){
        int y = tid/10, xo = tid%10;
        int g = 20*xo + y;
        float s = sacc[tid] + cbuf[(g%19)*10 + (g/19)];
        s = bnf(s, bnm, c, 64);
        sacc[tid] = 1.f/(1.f + __expf(-s));
    }
    __syncthreads();
    float* op = g_b2 + (size_t)bc*Ll;
    for (int p=tid; p<Ll; p+=256){
        int y = p/28, xx = p%28;
        op[p] = x2[p] * sacc[(y*10/28)*10 + (xx*10/28)];
    }
}

// ---------------- branch 3 ----------------
// bcdt pw (192x64), weight-stationary, register-blocked 4o x 10px
__global__ void __launch_bounds__(240,1)
k_bcdt_t(const float* __restrict__ x, const float* __restrict__ w){
    extern __shared__ float sm[];
    float* sw = sm;            // 192*65
    float* sx = sw + 192*65;   // 64*49
    int b = blockIdx.x / NTt, p0 = (blockIdx.x % NTt) * PT;
    int tid = threadIdx.x;
    for (int i=tid; i<192*64; i+=240){ sw[(i/64)*65 + (i%64)] = w[i]; }
    for (int i=tid; i<64*PT; i+=240){
        int c=i/PT, px=i%PT;
        sx[i] = x[((size_t)(b*DIMc + 128 + c))*Ll + p0+px];
    }
    __syncthreads();
    int og = tid % 48, pg = tid / 48;       // 48 o-groups x 5 px-groups
    int o0 = og*4, px0 = pg*10;
    int cnt = min(10, PT - px0);
    float acc[4][10];
    #pragma unroll
    for (int k=0;k<4;k++)
        #pragma unroll
        for (int j=0;j<10;j++) acc[k][j]=0.f;
    for (int c=0;c<64;c++){
        float w0=sw[(o0+0)*65+c], w1=sw[(o0+1)*65+c], w2=sw[(o0+2)*65+c], w3=sw[(o0+3)*65+c];
        #pragma unroll 10
        for (int j=0;j<10;j++){
            if (j<cnt){
                float xx = sx[c*PT + px0 + j];
                acc[0][j]+=w0*xx; acc[1][j]+=w1*xx; acc[2][j]+=w2*xx; acc[3][j]+=w3*xx;
            }
        }
    }
    #pragma unroll
    for (int k=0;k<4;k++)
        for (int j=0;j<cnt;j++)
            g_bcdt1[((size_t)(b*192 + o0+k))*Ll + p0+px0+j] = acc[k][j];
}

__global__ void k_dw3(const float* __restrict__ w){
    int idx = blockIdx.x*256 + threadIdx.x;
    if (idx >= Bq*192*Ll) return;
    int p = idx%Ll, c = (idx/Ll)%192, b = idx/(Ll*192);
    int y = p/28, x = p%28;
    const float* ip = g_bcdt1 + ((size_t)b*192 + c)*Ll;
    const float* wc = w + c*9;
    float acc = 0.f;
    #pragma unroll
    for (int ky=0; ky<3; ky++){ int yy=y+ky-1; if ((unsigned)yy>=28u) continue;
        #pragma unroll
        for (int kx=0; kx<3; kx++){ int xx=x+kx-1; if ((unsigned)xx>=28u) continue;
            acc += wc[ky*3+kx]*ip[yy*28+xx]; } }
    g_bcdt2[idx] = acc;
}

__global__ void k_softAB(const float* __restrict__ Ap){
    __shared__ float red[256];
    int bs = blockIdx.x; int b = bs/64, s = bs%64;
    int tid = threadIdx.x;
    const float av = Ap[s];
    const float* dt = g_bcdt2 + ((size_t)b*192 + 128 + s)*Ll;
    const float* Bm = g_bcdt2 + ((size_t)b*192 + s)*Ll;
    float m = -1e30f;
    for (int l=tid; l<Ll; l+=256) m = fmaxf(m, dt[l] + av);
    red[tid] = m; __syncthreads();
    for (int o=128; o>0; o>>=1){ if (tid<o) red[tid]=fmaxf(red[tid],red[tid+o]); __syncthreads(); }
    m = red[0]; __syncthreads();
    float sum = 0.f;
    for (int l=tid; l<Ll; l+=256) sum += __expf(dt[l] + av - m);
    red[tid] = sum; __syncthreads();
    for (int o=128; o>0; o>>=1){ if (tid<o) red[tid]+=red[tid+o]; __syncthreads(); }
    float inv = 1.f/red[0];
    float* wo = g_wsl + ((size_t)b*64 + s)*Ll;
    for (int l=tid; l<Ll; l+=256) wo[l] = __expf(dt[l] + av - m)*inv*Bm[l];
}

__global__ void k_h(const float* __restrict__ x){
    __shared__ float wr[Ll];
    int bs = blockIdx.x; int b = bs/64, s = bs%64;
    int tid = threadIdx.x;
    const float* wp = g_wsl + ((size_t)b*64 + s)*Ll;
    for (int l=tid; l<Ll; l+=64) wr[l] = wp[l];
    __syncthreads();
    const float* xs = x + ((size_t)(b*DIMc + 128 + tid))*Ll;
    float acc = 0.f;
    #pragma unroll 4
    for (int l=0; l<Ll; l++) acc += xs[l]*wr[l];
    g_h[((size_t)b*64 + tid)*64 + s] = acc;
}

__global__ void k_hz(const float* __restrict__ hzw, const float* __restrict__ outw,
                     const float* __restrict__ Dp){
    __shared__ float hc[64], hzv[128], gs[64];
    int bs = blockIdx.x; int b = bs/64, s = bs%64;
    int tid = threadIdx.x;
    if (tid < 64) hc[tid] = g_h[((size_t)b*64 + tid)*64 + s];
    __syncthreads();
    float acc = 0.f; const float* wr = hzw + tid*64;
    #pragma unroll 8
    for (int c=0;c<64;c++) acc += wr[c]*hc[c];
    hzv[tid] = acc;
    __syncthreads();
    if (tid < 64){
        float hv = hzv[tid], z = hzv[64+tid];
        gs[tid] = hv * (z/(1.f+__expf(-z))) + hv*Dp[0];
    }
    __syncthreads();
    if (tid < 64){
        float a2 = 0.f; const float* wo = outw + tid*64;
        #pragma unroll 8
        for (int c=0;c<64;c++) a2 += wo[c]*gs[c];
        g_h2[((size_t)b*64 + tid)*64 + s] = a2;
    }
}

__global__ void k_x3(){
    __shared__ float cs[64*112];
    int b = blockIdx.x; int l0 = blockIdx.y*112;
    int tid = threadIdx.x;
    for (int i=tid; i<64*112; i+=256){
        int s = i/112, lo = i%112;
        cs[i] = g_bcdt2[((size_t)b*192 + 64 + s)*Ll + l0 + lo];
    }
    __syncthreads();
    for (int i=tid; i<64*112; i+=256){
        int c = i/112, lo = i%112;
        const float* hr = g_h2 + ((size_t)b*64 + c)*64;
        float acc = 0.f;
        #pragma unroll 8
        for (int s=0; s<64; s++) acc += hr[s]*cs[s*112+lo];
        g_b3[((size_t)b*64 + c)*Ll + l0 + lo] = acc;
    }
}

// ---------------- branch 4 ----------------
// qkv pw (192x64), weight-stationary, scatter store
__global__ void __launch_bounds__(240,1)
k_qkv_t(const float* __restrict__ x, const float* __restrict__ w){
    extern __shared__ float sm[];
    float* sw = sm;            // 192*65
    float* sx = sw + 192*65;   // 64*49
    int b = blockIdx.x / NTt, p0 = (blockIdx.x % NTt) * PT;
    int tid = threadIdx.x;
    for (int i=tid; i<192*64; i+=240){ sw[(i/64)*65 + (i%64)] = w[i]; }
    for (int i=tid; i<64*PT; i+=240){
        int c=i/PT, px=i%PT;
        sx[i] = x[((size_t)(b*DIMc + 192 + c))*Ll + p0+px];
    }
    __syncthreads();
    int og = tid % 48, pg = tid / 48;
    int o0 = og*4, px0 = pg*10;
    int cnt = min(10, PT - px0);
    float acc[4][10];
    #pragma unroll
    for (int k=0;k<4;k++)
        #pragma unroll
        for (int j=0;j<10;j++) acc[k][j]=0.f;
    for (int c=0;c<64;c++){
        float w0=sw[(o0+0)*65+c], w1=sw[(o0+1)*65+c], w2=sw[(o0+2)*65+c], w3=sw[(o0+3)*65+c];
        #pragma unroll 10
        for (int j=0;j<10;j++){
            if (j<cnt){
                float xx = sx[c*PT + px0 + j];
                acc[0][j]+=w0*xx; acc[1][j]+=w1*xx; acc[2][j]+=w2*xx; acc[3][j]+=w3*xx;
            }
        }
    }
    #pragma unroll
    for (int k=0;k<4;k++){
        int o = o0+k;
        int part = o/64, rem = o%64, hh = rem/4, dd = rem%4;
        float* dst = (part==0) ? g_qb : (part==1) ? g_kb : g_vb;
        for (int j=0;j<cnt;j++)
            dst[(((size_t)b*16 + hh)*Ll + p0+px0+j)*4 + dd] = acc[k][j];
    }
}

__global__ void k_attn(){
    __shared__ float Ks[Ll*4], Vs[Ll*4];
    int bh = blockIdx.x;
    size_t base = (size_t)bh * Ll * 4;
    int tid = threadIdx.x;
    for (int i=tid; i<Ll*4; i+=Ll){ Ks[i] = g_kb[base+i]; Vs[i] = g_vb[base+i]; }
    __syncthreads();
    float q0 = g_qb[base + tid*4 + 0];
    float q1 = g_qb[base + tid*4 + 1];
    float q2 = g_qb[base + tid*4 + 2];
    float q3 = g_qb[base + tid*4 + 3];
    float mx = -1e30f;
    #pragma unroll 4
    for (int j=0; j<Ll; j++){
        float s = 0.5f*(q0*Ks[j*4] + q1*Ks[j*4+1] + q2*Ks[j*4+2] + q3*Ks[j*4+3]);
        mx = fmaxf(mx, s);
    }
    float den = 0.f, a0 = 0.f, a1 = 0.f, a2 = 0.f, a3 = 0.f;
    #pragma unroll 4
    for (int j=0; j<Ll; j++){
        float s = 0.5f*(q0*Ks[j*4] + q1*Ks[j*4+1] + q2*Ks[j*4+2] + q3*Ks[j*4+3]);
        float e = __expf(s - mx);
        den += e;
        a0 += e*Vs[j*4]; a1 += e*Vs[j*4+1]; a2 += e*Vs[j*4+2]; a3 += e*Vs[j*4+3];
    }
    float inv = 1.f/den;
    int b = bh/16, hh = bh%16;
    float* op = g_ob + ((size_t)b*Ll + tid)*64 + hh*4;
    op[0] = a0*inv; op[1] = a1*inv; op[2] = a2*inv; op[3] = a3*inv;
}

// proj (64x64) + residual + BN, weight-stationary
__global__ void __launch_bounds__(256,1)
k_proj_t(const float* __restrict__ x, const float* __restrict__ pw,
         const float* __restrict__ bnp){
    extern __shared__ float sm[];
    float* sw = sm;            // 64*65
    float* sx = sw + 64*65;    // 64*49
    float* sbn = sx + 64*PT;   // 256
    int b = blockIdx.x / NTt, p0 = (blockIdx.x % NTt) * PT;
    int tid = threadIdx.x;
    for (int i=tid; i<64*64; i+=256){ sw[(i/64)*65 + (i%64)] = pw[i]; }
    sbn[tid] = bnp[tid];
    for (int i=tid; i<64*PT; i+=256){
        int c=i%64, px=i/64;
        sx[c*PT+px] = g_ob[((size_t)b*Ll + p0+px)*64 + c];
    }
    __syncthreads();
    for (int i=tid; i<64*PT; i+=256){
        int o=i/PT, px=i%PT;
        float acc = 0.f;
        const float* wr = sw + o*65;
        #pragma unroll 8
        for (int j=0;j<64;j++) acc += wr[j]*sx[j*PT+px];
        float xv = x[((size_t)(b*DIMc + 192 + o))*Ll + p0+px];
        g_b4[((size_t)(b*64+o))*Ll + p0+px] = bnf(xv + acc, sbn, o, 64);
    }
}

// ---------------- merge MLP ----------------
// mlp1 (128x256) + BN + relu, register-blocked 4o x 7px
__global__ void __launch_bounds__(256,1)
k_mlp1_t(const float* __restrict__ w, const float* __restrict__ bnp){
    extern __shared__ float sm[];
    float* sw = sm;              // 128*257
    float* sx = sw + 128*257;    // 256*49
    float* sbn = sx + 256*PT;    // 512
    int b = blockIdx.x / NTt, p0 = (blockIdx.x % NTt) * PT;
    int tid = threadIdx.x;
    for (int i=tid; i<128*256; i+=256){ sw[(i/256)*257 + (i%256)] = w[i]; }
    for (int i=tid; i<512; i+=256) sbn[i] = bnp[i];
    for (int i=tid; i<256*PT; i+=256){
        int c=i/PT, px=i%PT;
        const float* src = (c<64) ? g_b1 : (c<128) ? g_b2 : (c<192) ? g_b3 : g_b4;
        sx[i] = src[((size_t)(b*64 + (c&63)))*Ll + p0+px];
    }
    __syncthreads();
    int ot = tid % 32, pg = tid / 32;       // 32 o-groups x 8 px-groups
    int o0 = ot*4, px0 = pg*7;
    int cnt = (px0 < PT) ? min(7, PT - px0) : 0;
    float acc[4][7];
    #pragma unroll
    for (int k=0;k<4;k++)
        #pragma unroll
        for (int j=0;j<7;j++) acc[k][j]=0.f;
    for (int c=0;c<256;c++){
        float w0=sw[(o0+0)*257+c], w1=sw[(o0+1)*257+c], w2=sw[(o0+2)*257+c], w3=sw[(o0+3)*257+c];
        #pragma unroll 7
        for (int j=0;j<7;j++){
            if (j<cnt){
                float xx = sx[c*PT + px0 + j];
                acc[0][j]+=w0*xx; acc[1][j]+=w1*xx; acc[2][j]+=w2*xx; acc[3][j]+=w3*xx;
            }
        }
    }
    #pragma unroll
    for (int k=0;k<4;k++)
        for (int j=0;j<cnt;j++){
            float v = bnf(acc[k][j], sbn, o0+k, 128);
            g_m1[((size_t)(b*128 + o0+k))*Ll + p0+px0+j] = fmaxf(v, 0.f);
        }
}

// mlp2 (256x128) + BN + residual, register-blocked 4o x 13px
__global__ void __launch_bounds__(256,1)
k_mlp2_t(const float* __restrict__ x, const float* __restrict__ w,
         const float* __restrict__ bnp, float* __restrict__ out){
    extern __shared__ float sm[];
    float* sw = sm;              // 256*129
    float* sx = sw + 256*129;    // 128*49
    float* sbn = sx + 128*PT;    // 1024
    int b = blockIdx.x / NTt, p0 = (blockIdx.x % NTt) * PT;
    int tid = threadIdx.x;
    for (int i=tid; i<256*128; i+=256){ sw[(i/128)*129 + (i%128)] = w[i]; }
    for (int i=tid; i<1024; i+=256) sbn[i] = bnp[i];
    for (int i=tid; i<128*PT; i+=256){
        int c=i/PT, px=i%PT;
        sx[i] = g_m1[((size_t)(b*128 + c))*Ll + p0+px];
    }
    __syncthreads();
    int og = tid % 64, pg = tid / 64;       // 64 o-groups x 4 px-groups
    int o0 = og*4, px0 = pg*13;
    int cnt = min(13, PT - px0);
    float acc[4][13];
    #pragma unroll
    for (int k=0;k<4;k++)
        #pragma unroll
        for (int j=0;j<13;j++) acc[k][j]=0.f;
    for (int c=0;c<128;c++){
        float w0=sw[(o0+0)*129+c], w1=sw[(o0+1)*129+c], w2=sw[(o0+2)*129+c], w3=sw[(o0+3)*129+c];
        #pragma unroll 13
        for (int j=0;j<13;j++){
            if (j<cnt){
                float xx = sx[c*PT + px0 + j];
                acc[0][j]+=w0*xx; acc[1][j]+=w1*xx; acc[2][j]+=w2*xx; acc[3][j]+=w3*xx;
            }
        }
    }
    #pragma unroll
    for (int k=0;k<4;k++)
        for (int j=0;j<cnt;j++){
            size_t idx = ((size_t)(b*DIMc + o0+k))*Ll + p0+px0+j;
            out[idx] = x[idx] + bnf(acc[k][j], sbn, o0+k, 256);
        }
}

// ---------------- launch ----------------
extern "C" void kernel_launch(void* const* d_in, const int* in_sizes, int n_in,
                              void* d_out, int out_size){
    const float* x       = (const float*)d_in[0];
    const float* dw1_w   = (const float*)d_in[1];
    const float* dw1_b   = (const float*)d_in[2];
    const float* bn_dw1  = (const float*)d_in[3];
    const float* f1_w    = (const float*)d_in[4];
    const float* f1_b    = (const float*)d_in[5];
    const float* f2_w    = (const float*)d_in[6];
    const float* f2_b    = (const float*)d_in[7];
    const float* g_w     = (const float*)d_in[8];
    const float* g_b     = (const float*)d_in[9];
    const float* bn_g    = (const float*)d_in[10];
    const float* dw2_w   = (const float*)d_in[11];
    const float* dw2_b   = (const float*)d_in[12];
    const float* hatt1_w = (const float*)d_in[13];
    const float* vatt1_w = (const float*)d_in[14];
    const float* hatt2_w = (const float*)d_in[15];
    const float* vatt2_w = (const float*)d_in[16];
    const float* bn_mra  = (const float*)d_in[17];
    const float* bcdt_w  = (const float*)d_in[18];
    const float* ssd_dw_w= (const float*)d_in[19];
    const float* hz_w    = (const float*)d_in[20];
    const float* out_w   = (const float*)d_in[21];
    const float* A_param = (const float*)d_in[22];
    const float* D_param = (const float*)d_in[23];
    const float* qkv_w   = (const float*)d_in[24];
    const float* proj_w  = (const float*)d_in[25];
    const float* bn_n4   = (const float*)d_in[26];
    const float* mlp1_w  = (const float*)d_in[27];
    const float* bn_mlp  = (const float*)d_in[28];
    const float* mlp2_w  = (const float*)d_in[29];
    const float* bn_n1   = (const float*)d_in[30];
    float* out = (float*)d_out;
    (void)n_in; (void)in_sizes; (void)out_size;

    const int NE  = Bq*Cc*Ll;       // 401408
    const int NE3 = Bq*192*Ll;      // 1204224
    const int TB  = Bq*NTt;         // 128 tile blocks

    // dynamic smem sizes (bytes)
    const int SM_STAR = (8192*3 + 128 + 128 + 64 + 256 + 64*PT + 128*PT) * 4;
    const int SM_BCDT = (192*65 + 64*PT) * 4;
    const int SM_PROJ = (64*65 + 64*PT + 256) * 4;
    const int SM_MLP1 = (128*257 + 256*PT + 512) * 4;
    const int SM_MLP2 = (256*129 + 128*PT + 1024) * 4;

    cudaFuncSetAttribute(k_star_t, cudaFuncAttributeMaxDynamicSharedMemorySize, SM_STAR);
    cudaFuncSetAttribute(k_bcdt_t, cudaFuncAttributeMaxDynamicSharedMemorySize, SM_BCDT);
    cudaFuncSetAttribute(k_qkv_t,  cudaFuncAttributeMaxDynamicSharedMemorySize, SM_BCDT);
    cudaFuncSetAttribute(k_mlp1_t, cudaFuncAttributeMaxDynamicSharedMemorySize, SM_MLP1);
    cudaFuncSetAttribute(k_mlp2_t, cudaFuncAttributeMaxDynamicSharedMemorySize, SM_MLP2);

    // branch 1
    k_dw7a<<<(NE+255)/256, 256>>>(x, dw1_w, dw1_b, bn_dw1);
    k_star_t<<<TB, 256, SM_STAR>>>(f1_w, f1_b, f2_w, f2_b, g_w, g_b, bn_g);
    k_dw7b<<<(NE+255)/256, 256>>>(dw2_w, dw2_b);

    // branch 2 (maxpool fused)
    k_att2<<<Bq*Cc, 256>>>(x, hatt1_w, vatt1_w, hatt2_w, vatt2_w, bn_mra);

    // branch 3
    k_bcdt_t<<<TB, 240, SM_BCDT>>>(x, bcdt_w);
    k_dw3<<<(NE3+255)/256, 256>>>(ssd_dw_w);
    k_softAB<<<Bq*Sdim, 256>>>(A_param);
    k_h<<<Bq*Sdim, 64>>>(x);
    k_hz<<<Bq*Sdim, 128>>>(hz_w, out_w, D_param);
    k_x3<<<dim3(Bq, 7), 256>>>();

    // branch 4
    k_qkv_t<<<TB, 240, SM_BCDT>>>(x, qkv_w);
    k_attn<<<Bq*NHh, Ll>>>();
    k_proj_t<<<TB, 256, SM_PROJ>>>(x, proj_w, bn_n4);

    // merge MLP
    k_mlp1_t<<<TB, 256, SM_MLP1>>>(mlp1_w, bn_mlp);
    k_mlp2_t<<<TB, 256, SM_MLP2>>>(x, mlp2_w, bn_n1, out);
}

// round 10
// speedup vs baseline: 7.7232x; 1.2589x over previous
#include <cuda_runtime.h>
#include <math.h>

#define Bq 8
#define Cc 64
#define Ll 784
#define HIDd 128
#define Sdim 64
#define NHh 16
#define DIMc 256
#define PT 49
#define NTt 16

// ---------------- scratch ----------------
__device__ float g_x1o [Bq*Cc*Ll];
__device__ float g_x1g [Bq*Cc*Ll];
__device__ float g_b1  [Bq*Cc*Ll];
__device__ float g_b2  [Bq*Cc*Ll];
__device__ float g_bcdt1[Bq*192*Ll];
__device__ float g_bcdt2[Bq*192*Ll];
__device__ float g_wsl [Bq*Sdim*Ll];
__device__ float g_h   [Bq*Cc*Sdim];
__device__ float g_h2  [Bq*Cc*Sdim];
__device__ float g_b3  [Bq*Cc*Ll];
__device__ float g_qb  [Bq*NHh*Ll*4];
__device__ float g_kb  [Bq*NHh*Ll*4];
__device__ float g_vb  [Bq*NHh*Ll*4];
__device__ float g_ob  [Bq*Ll*Cc];
__device__ float g_b4  [Bq*Cc*Ll];
__device__ float g_m1  [Bq*HIDd*Ll];

__device__ __forceinline__ float bnf(float x, const float* __restrict__ p, int c, int C){
    return (x - p[2*C+c]) * p[c] * rsqrtf(p[3*C+c] + 1e-5f) + p[C+c];
}

// f32x2 packed helpers (sm_103a FFMA2 via PTX)
__device__ __forceinline__ unsigned long long pk2(float a, float b){
    unsigned long long r; asm("mov.b64 %0, {%1,%2};" : "=l"(r) : "f"(a), "f"(b)); return r;
}
__device__ __forceinline__ void upk2(unsigned long long v, float& a, float& b){
    asm("mov.b64 {%0,%1}, %2;" : "=f"(a), "=f"(b) : "l"(v));
}
__device__ __forceinline__ unsigned long long fma2(unsigned long long a, unsigned long long b, unsigned long long c){
    unsigned long long r; asm("fma.rn.f32x2 %0, %1, %2, %3;" : "=l"(r) : "l"(a), "l"(b), "l"(c)); return r;
}
__device__ __forceinline__ unsigned long long mul2(unsigned long long a, unsigned long long b){
    unsigned long long r; asm("mul.rn.f32x2 %0, %1, %2;" : "=l"(r) : "l"(a), "l"(b)); return r;
}

// ---------------- branch 1 ----------------
__global__ void k_dw7a(const float* __restrict__ x, const float* __restrict__ w,
                       const float* __restrict__ bias, const float* __restrict__ bnp){
    int idx = blockIdx.x*256 + threadIdx.x;
    if (idx >= Bq*Cc*Ll) return;
    int p = idx % Ll; int c = (idx/Ll) % Cc; int b = idx/(Ll*Cc);
    int y = p/28, xx = p%28;
    const float* ip = x + ((size_t)(b*DIMc + c))*Ll;
    const float* wc = w + c*49;
    float acc = bias[c];
    #pragma unroll
    for (int ky=0; ky<7; ky++){
        int yy = y+ky-3; if ((unsigned)yy >= 28u) continue;
        #pragma unroll
        for (int kx=0; kx<7; kx++){
            int xw = xx+kx-3; if ((unsigned)xw >= 28u) continue;
            acc += wc[ky*7+kx] * ip[yy*28+xw];
        }
    }
    g_x1o[idx] = bnf(acc, bnp, c, Cc);
}

__global__ void k_dw7b(const float* __restrict__ w, const float* __restrict__ bias){
    int idx = blockIdx.x*256 + threadIdx.x;
    if (idx >= Bq*Cc*Ll) return;
    int p = idx % Ll; int c = (idx/Ll) % Cc; int b = idx/(Ll*Cc);
    int y = p/28, xx = p%28;
    const float* ip = g_x1g + ((size_t)(b*Cc + c))*Ll;
    const float* wc = w + c*49;
    float acc = bias[c];
    #pragma unroll
    for (int ky=0; ky<7; ky++){
        int yy = y+ky-3; if ((unsigned)yy >= 28u) continue;
        #pragma unroll
        for (int kx=0; kx<7; kx++){
            int xw = xx+kx-3; if ((unsigned)xw >= 28u) continue;
            acc += wc[ky*7+kx] * ip[yy*28+xw];
        }
    }
    g_b1[idx] = acc;
}

__global__ void __launch_bounds__(256,1)
k_star_t(const float* __restrict__ f1w, const float* __restrict__ f1b,
         const float* __restrict__ f2w, const float* __restrict__ f2b,
         const float* __restrict__ gw,  const float* __restrict__ gb,
         const float* __restrict__ bng){
    extern __shared__ float sm[];
    float* sf1 = sm;
    float* sf2 = sf1 + 8192;
    float* sg  = sf2 + 8192;
    float* sb1 = sg  + 8192;
    float* sb2 = sb1 + 128;
    float* sgb = sb2 + 128;
    float* sbn = sgb + 64;
    float* sxv = sbn + 256;
    float* sts = sxv + 64*PT;
    int b = blockIdx.x / NTt, p0 = (blockIdx.x % NTt) * PT;
    int tid = threadIdx.x;
    for (int i=tid; i<8192; i+=256){ sf1[i]=f1w[i]; sf2[i]=f2w[i]; sg[i]=gw[i]; }
    if (tid<128){ sb1[tid]=f1b[tid]; sb2[tid]=f2b[tid]; }
    if (tid<64) sgb[tid]=gb[tid];
    sbn[tid] = bng[tid];
    for (int i=tid; i<64*PT; i+=256){
        int c=i/PT, px=i%PT;
        sxv[i] = g_x1o[((size_t)(b*64+c))*Ll + p0+px];
    }
    __syncthreads();
    for (int i=tid; i<128*PT; i+=256){
        int h=i/PT, px=i%PT;
        float a1=sb1[h], a2=sb2[h];
        const float* w1=sf1+h*64; const float* w2=sf2+h*64;
        #pragma unroll 8
        for (int c=0;c<64;c++){ float xc=sxv[c*PT+px]; a1+=w1[c]*xc; a2+=w2[c]*xc; }
        a1 = fminf(fmaxf(a1,0.f),6.f);
        sts[i] = a1*a2;
    }
    __syncthreads();
    for (int i=tid; i<64*PT; i+=256){
        int o=i/PT, px=i%PT;
        float acc=sgb[o];
        const float* wg=sg+o*128;
        #pragma unroll 8
        for (int j=0;j<128;j++) acc += wg[j]*sts[j*PT+px];
        g_x1g[((size_t)(b*64+o))*Ll + p0+px] = bnf(acc, sbn, o, 64);
    }
}

// ---------------- branch 2 ----------------
__global__ void k_att2(const float* __restrict__ x,
                       const float* __restrict__ wh1, const float* __restrict__ wv1,
                       const float* __restrict__ wh2, const float* __restrict__ wv2,
                       const float* __restrict__ bnm){
    __shared__ float mp[784], xt[100], sacc[100], sh[190], cbuf[190];
    __shared__ float sw1[33], sw2[33], sw3[33], sw4[33];
    int bc = blockIdx.x; int b = bc/64, c = bc%64;
    int tid = threadIdx.x;
    if (tid < 33){ sw1[tid]=wh1[c*33+tid]; sw2[tid]=wv1[c*33+tid];
                   sw3[tid]=wh2[c*33+tid]; sw4[tid]=wv2[c*33+tid]; }
    const float* x2 = x + ((size_t)(b*DIMc + 64 + c))*Ll;
    for (int p=tid; p<784; p+=256){
        int y=p/28, xx=p%28;
        float m = -1e30f;
        #pragma unroll
        for (int dy=-1; dy<=1; dy++){ int yy=y+dy; if ((unsigned)yy>=28u) continue;
            #pragma unroll
            for (int dx=-1; dx<=1; dx++){ int xw=xx+dx; if ((unsigned)xw>=28u) continue;
                m = fmaxf(m, x2[yy*28+xw]); } }
        mp[p] = m;
    }
    __syncthreads();
    if (tid < 100){
        int oy = tid/10, ox = tid%10;
        const float fa[4] = {1.f,3.f,3.f,1.f};
        float acc = 0.f;
        #pragma unroll
        for (int ty=0; ty<4; ty++){
            int q = 3*oy + ty - 1; if (q < 0) q = -q; if (q >= 28) q = 54 - q;
            #pragma unroll
            for (int tx=0; tx<4; tx++){
                int r = 3*ox + tx - 1; if (r < 0) r = -r; if (r >= 28) r = 54 - r;
                acc += fa[ty]*fa[tx]*mp[q*28+r];
            }
        }
        xt[tid] = acc * (1.0f/64.0f);
    }
    __syncthreads();
    if (tid < 100){
        int y = tid/10, xo = tid%10;
        float s = 0.f;
        #pragma unroll
        for (int ky=0; ky<11; ky++){ int yy=y+ky-5; if ((unsigned)yy>=10u) continue;
            #pragma unroll
            for (int kx=0; kx<3; kx++){ int xx=xo+kx-1; if ((unsigned)xx>=10u) continue;
                s += sw1[ky*3+kx]*xt[yy*10+xx]; } }
        #pragma unroll
        for (int ky=0; ky<3; ky++){ int yy=y+ky-1; if ((unsigned)yy>=10u) continue;
            #pragma unroll
            for (int kx=0; kx<11; kx++){ int xx=xo+kx-5; if ((unsigned)xx>=10u) continue;
                s += sw2[ky*11+kx]*xt[yy*10+xx]; } }
        sacc[tid] = s;
    }
    if (tid < 190){
        int r = tid/19, j = tid%19, d = j - r;
        sh[tid] = (d >= 0 && d < 10) ? xt[r*10 + d] : 0.f;
    }
    __syncthreads();
    if (tid < 190){
        int u = tid/19, v = tid%19;
        float s = 0.f;
        #pragma unroll
        for (int ky=0; ky<11; ky++){ int uu=u+ky-5; if ((unsigned)uu>=10u) continue;
            #pragma unroll
            for (int kx=0; kx<3; kx++){ int vv=v+kx-1; if ((unsigned)vv>=19u) continue;
                s += sw3[ky*3+kx]*sh[uu*19+vv]; } }
        cbuf[tid] = s;
    }
    __syncthreads();
    if (tid < 100){
        int y = tid/10, xo = tid%10;
        sacc[tid] += cbuf[20*y + xo];
    }
    __syncthreads();
    if (tid < 190){
        int a = tid/10, b2 = tid%10, d = a - b2;
        sh[tid] = (d >= 0 && d < 10) ? xt[d*10 + b2] : 0.f;
    }
    __syncthreads();
    if (tid < 190){
        int a = tid/10, b2 = tid%10;
        float s = 0.f;
        #pragma unroll
        for (int ky=0; ky<3; ky++){ int av=a+ky-1; if ((unsigned)av>=19u) continue;
            #pragma unroll
            for (int kx=0; kx<11; kx++){ int bv=b2+kx-5; if ((unsigned)bv>=10u) continue;
                s += sw4[ky*11+kx]*sh[av*10+bv]; } }
        cbuf[tid] = s;
    }
    __syncthreads();
    if (tid < 100){
        int y = tid/10, xo = tid%10;
        int g = 20*xo + y;
        float s = sacc[tid] + cbuf[(g%19)*10 + (g/19)];
        s = bnf(s, bnm, c, 64);
        sacc[tid] = 1.f/(1.f + __expf(-s));
    }
    __syncthreads();
    float* op = g_b2 + (size_t)bc*Ll;
    for (int p=tid; p<Ll; p+=256){
        int y = p/28, xx = p%28;
        op[p] = x2[p] * sacc[(y*10/28)*10 + (xx*10/28)];
    }
}

// ---------------- branch 3 ----------------
__global__ void __launch_bounds__(240,1)
k_bcdt_t(const float* __restrict__ x, const float* __restrict__ w){
    extern __shared__ float sm[];
    float* sw = sm;
    float* sx = sw + 192*65;
    int b = blockIdx.x / NTt, p0 = (blockIdx.x % NTt) * PT;
    int tid = threadIdx.x;
    for (int i=tid; i<192*64; i+=240){ sw[(i/64)*65 + (i%64)] = w[i]; }
    for (int i=tid; i<64*PT; i+=240){
        int c=i/PT, px=i%PT;
        sx[i] = x[((size_t)(b*DIMc + 128 + c))*Ll + p0+px];
    }
    __syncthreads();
    int og = tid % 48, pg = tid / 48;
    int o0 = og*4, px0 = pg*10;
    int cnt = min(10, PT - px0);
    float acc[4][10];
    #pragma unroll
    for (int k=0;k<4;k++)
        #pragma unroll
        for (int j=0;j<10;j++) acc[k][j]=0.f;
    for (int c=0;c<64;c++){
        float w0=sw[(o0+0)*65+c], w1=sw[(o0+1)*65+c], w2=sw[(o0+2)*65+c], w3=sw[(o0+3)*65+c];
        #pragma unroll 10
        for (int j=0;j<10;j++){
            if (j<cnt){
                float xx = sx[c*PT + px0 + j];
                acc[0][j]+=w0*xx; acc[1][j]+=w1*xx; acc[2][j]+=w2*xx; acc[3][j]+=w3*xx;
            }
        }
    }
    #pragma unroll
    for (int k=0;k<4;k++)
        for (int j=0;j<cnt;j++)
            g_bcdt1[((size_t)(b*192 + o0+k))*Ll + p0+px0+j] = acc[k][j];
}

__global__ void k_dw3(const float* __restrict__ w){
    int idx = blockIdx.x*256 + threadIdx.x;
    if (idx >= Bq*192*Ll) return;
    int p = idx%Ll, c = (idx/Ll)%192, b = idx/(Ll*192);
    int y = p/28, x = p%28;
    const float* ip = g_bcdt1 + ((size_t)b*192 + c)*Ll;
    const float* wc = w + c*9;
    float acc = 0.f;
    #pragma unroll
    for (int ky=0; ky<3; ky++){ int yy=y+ky-1; if ((unsigned)yy>=28u) continue;
        #pragma unroll
        for (int kx=0; kx<3; kx++){ int xx=x+kx-1; if ((unsigned)xx>=28u) continue;
            acc += wc[ky*3+kx]*ip[yy*28+xx]; } }
    g_bcdt2[idx] = acc;
}

__global__ void k_softAB(const float* __restrict__ Ap){
    __shared__ float red[256];
    int bs = blockIdx.x; int b = bs/64, s = bs%64;
    int tid = threadIdx.x;
    const float av = Ap[s];
    const float* dt = g_bcdt2 + ((size_t)b*192 + 128 + s)*Ll;
    const float* Bm = g_bcdt2 + ((size_t)b*192 + s)*Ll;
    float m = -1e30f;
    for (int l=tid; l<Ll; l+=256) m = fmaxf(m, dt[l] + av);
    red[tid] = m; __syncthreads();
    for (int o=128; o>0; o>>=1){ if (tid<o) red[tid]=fmaxf(red[tid],red[tid+o]); __syncthreads(); }
    m = red[0]; __syncthreads();
    float sum = 0.f;
    for (int l=tid; l<Ll; l+=256) sum += __expf(dt[l] + av - m);
    red[tid] = sum; __syncthreads();
    for (int o=128; o>0; o>>=1){ if (tid<o) red[tid]+=red[tid+o]; __syncthreads(); }
    float inv = 1.f/red[0];
    float* wo = g_wsl + ((size_t)b*64 + s)*Ll;
    for (int l=tid; l<Ll; l+=256) wo[l] = __expf(dt[l] + av - m)*inv*Bm[l];
}

// h[b][c][s] = sum_l x[b,128+c,l] * wsl[b,s,l]  — tiled GEMM, grid (8, 2)
__global__ void __launch_bounds__(256,1)
k_hg(const float* __restrict__ x){
    __shared__ float sx[64*99];
    __shared__ float sw[32*99];
    int b = blockIdx.x, sh = blockIdx.y;
    int tid = threadIdx.x;
    int c0 = (tid & 15)*4, s0 = (tid >> 4)*2;
    float acc[4][2] = {};
    for (int ch=0; ch<8; ch++){
        int l0 = ch*98;
        for (int i=tid; i<64*98; i+=256){
            int c=i/98, l=i%98;
            sx[c*99+l] = x[((size_t)(b*DIMc + 128 + c))*Ll + l0 + l];
        }
        for (int i=tid; i<32*98; i+=256){
            int sr=i/98, l=i%98;
            sw[sr*99+l] = g_wsl[((size_t)(b*64 + sh*32 + sr))*Ll + l0 + l];
        }
        __syncthreads();
        #pragma unroll 2
        for (int l=0; l<98; l++){
            float w0 = sw[s0*99+l], w1 = sw[(s0+1)*99+l];
            #pragma unroll
            for (int k=0;k<4;k++){
                float xc = sx[(c0+k)*99+l];
                acc[k][0] += xc*w0;
                acc[k][1] += xc*w1;
            }
        }
        __syncthreads();
    }
    #pragma unroll
    for (int k=0;k<4;k++){
        g_h[((size_t)(b*64 + c0+k))*64 + sh*32 + s0]     = acc[k][0];
        g_h[((size_t)(b*64 + c0+k))*64 + sh*32 + s0 + 1] = acc[k][1];
    }
}

__global__ void k_hz(const float* __restrict__ hzw, const float* __restrict__ outw,
                     const float* __restrict__ Dp){
    __shared__ float hc[64], hzv[128], gs[64];
    int bs = blockIdx.x; int b = bs/64, s = bs%64;
    int tid = threadIdx.x;
    if (tid < 64) hc[tid] = g_h[((size_t)b*64 + tid)*64 + s];
    __syncthreads();
    float acc = 0.f; const float* wr = hzw + tid*64;
    #pragma unroll 8
    for (int c=0;c<64;c++) acc += wr[c]*hc[c];
    hzv[tid] = acc;
    __syncthreads();
    if (tid < 64){
        float hv = hzv[tid], z = hzv[64+tid];
        gs[tid] = hv * (z/(1.f+__expf(-z))) + hv*Dp[0];
    }
    __syncthreads();
    if (tid < 64){
        float a2 = 0.f; const float* wo = outw + tid*64;
        #pragma unroll 8
        for (int c=0;c<64;c++) a2 += wo[c]*gs[c];
        g_h2[((size_t)b*64 + tid)*64 + s] = a2;
    }
}

__global__ void k_x3(){
    __shared__ float cs[64*112];
    int b = blockIdx.x; int l0 = blockIdx.y*112;
    int tid = threadIdx.x;
    for (int i=tid; i<64*112; i+=256){
        int s = i/112, lo = i%112;
        cs[i] = g_bcdt2[((size_t)b*192 + 64 + s)*Ll + l0 + lo];
    }
    __syncthreads();
    for (int i=tid; i<64*112; i+=256){
        int c = i/112, lo = i%112;
        const float* hr = g_h2 + ((size_t)b*64 + c)*64;
        float acc = 0.f;
        #pragma unroll 8
        for (int s=0; s<64; s++) acc += hr[s]*cs[s*112+lo];
        g_b3[((size_t)b*64 + c)*Ll + l0 + lo] = acc;
    }
}

// ---------------- branch 4 ----------------
__global__ void __launch_bounds__(240,1)
k_qkv_t(const float* __restrict__ x, const float* __restrict__ w){
    extern __shared__ float sm[];
    float* sw = sm;
    float* sx = sw + 192*65;
    int b = blockIdx.x / NTt, p0 = (blockIdx.x % NTt) * PT;
    int tid = threadIdx.x;
    for (int i=tid; i<192*64; i+=240){ sw[(i/64)*65 + (i%64)] = w[i]; }
    for (int i=tid; i<64*PT; i+=240){
        int c=i/PT, px=i%PT;
        sx[i] = x[((size_t)(b*DIMc + 192 + c))*Ll + p0+px];
    }
    __syncthreads();
    int og = tid % 48, pg = tid / 48;
    int o0 = og*4, px0 = pg*10;
    int cnt = min(10, PT - px0);
    float acc[4][10];
    #pragma unroll
    for (int k=0;k<4;k++)
        #pragma unroll
        for (int j=0;j<10;j++) acc[k][j]=0.f;
    for (int c=0;c<64;c++){
        float w0=sw[(o0+0)*65+c], w1=sw[(o0+1)*65+c], w2=sw[(o0+2)*65+c], w3=sw[(o0+3)*65+c];
        #pragma unroll 10
        for (int j=0;j<10;j++){
            if (j<cnt){
                float xx = sx[c*PT + px0 + j];
                acc[0][j]+=w0*xx; acc[1][j]+=w1*xx; acc[2][j]+=w2*xx; acc[3][j]+=w3*xx;
            }
        }
    }
    #pragma unroll
    for (int k=0;k<4;k++){
        int o = o0+k;
        int part = o/64, rem = o%64, hh = rem/4, dd = rem%4;
        float* dst = (part==0) ? g_qb : (part==1) ? g_kb : g_vb;
        for (int j=0;j<cnt;j++)
            dst[(((size_t)b*16 + hh)*Ll + p0+px0+j)*4 + dd] = acc[k][j];
    }
}

// single-pass softmax attention (no max-sub; scores O(1)); f32x2 packed FMA
__global__ void __launch_bounds__(784,1) k_attn(){
    __shared__ ulonglong2 KV[Ll];   // K pair
    __shared__ ulonglong2 VV[Ll];   // V pair
    int bh = blockIdx.x;
    size_t base4 = (size_t)bh * Ll;   // float4 index
    int tid = threadIdx.x;
    KV[tid] = ((const ulonglong2*)g_kb)[base4 + tid];
    VV[tid] = ((const ulonglong2*)g_vb)[base4 + tid];
    __syncthreads();
    float4 q = ((const float4*)g_qb)[base4 + tid];
    const float CS = 0.7213475204444817f;   // 0.5 * log2(e)
    unsigned long long q01 = pk2(q.x*CS, q.y*CS);
    unsigned long long q23 = pk2(q.z*CS, q.w*CS);
    unsigned long long a01 = pk2(0.f,0.f), a23 = pk2(0.f,0.f);
    float den = 0.f;
    #pragma unroll 4
    for (int j=0; j<Ll; j++){
        ulonglong2 kk = KV[j];
        ulonglong2 vv = VV[j];
        unsigned long long pr = fma2(q23, kk.y, mul2(q01, kk.x));
        float lo, hi; upk2(pr, lo, hi);
        float s = lo + hi;
        float e; asm("ex2.approx.f32 %0, %1;" : "=f"(e) : "f"(s));
        unsigned long long ee = pk2(e, e);
        a01 = fma2(ee, vv.x, a01);
        a23 = fma2(ee, vv.y, a23);
        den += e;
    }
    float inv = __frcp_rn(den);
    float a0,a1,a2,a3;
    upk2(a01,a0,a1); upk2(a23,a2,a3);
    int b = bh/16, hh = bh%16;
    float4 r; r.x=a0*inv; r.y=a1*inv; r.z=a2*inv; r.w=a3*inv;
    ((float4*)g_ob)[(((size_t)b*Ll + tid)*64 + hh*4)/4] = r;
}

__global__ void __launch_bounds__(256,1)
k_proj_t(const float* __restrict__ x, const float* __restrict__ pw,
         const float* __restrict__ bnp){
    extern __shared__ float sm[];
    float* sw = sm;
    float* sx = sw + 64*65;
    float* sbn = sx + 64*PT;
    int b = blockIdx.x / NTt, p0 = (blockIdx.x % NTt) * PT;
    int tid = threadIdx.x;
    for (int i=tid; i<64*64; i+=256){ sw[(i/64)*65 + (i%64)] = pw[i]; }
    sbn[tid] = bnp[tid];
    for (int i=tid; i<64*PT; i+=256){
        int c=i%64, px=i/64;
        sx[c*PT+px] = g_ob[((size_t)b*Ll + p0+px)*64 + c];
    }
    __syncthreads();
    for (int i=tid; i<64*PT; i+=256){
        int o=i/PT, px=i%PT;
        float acc = 0.f;
        const float* wr = sw + o*65;
        #pragma unroll 8
        for (int j=0;j<64;j++) acc += wr[j]*sx[j*PT+px];
        float xv = x[((size_t)(b*DIMc + 192 + o))*Ll + p0+px];
        g_b4[((size_t)(b*64+o))*Ll + p0+px] = bnf(xv + acc, sbn, o, 64);
    }
}

// ---------------- merge MLP ----------------
__global__ void __launch_bounds__(256,1)
k_mlp1_t(const float* __restrict__ w, const float* __restrict__ bnp){
    extern __shared__ float sm[];
    float* sw = sm;
    float* sx = sw + 128*257;
    float* sbn = sx + 256*PT;
    int b = blockIdx.x / NTt, p0 = (blockIdx.x % NTt) * PT;
    int tid = threadIdx.x;
    for (int i=tid; i<128*256; i+=256){ sw[(i/256)*257 + (i%256)] = w[i]; }
    for (int i=tid; i<512; i+=256) sbn[i] = bnp[i];
    for (int i=tid; i<256*PT; i+=256){
        int c=i/PT, px=i%PT;
        const float* src = (c<64) ? g_b1 : (c<128) ? g_b2 : (c<192) ? g_b3 : g_b4;
        sx[i] = src[((size_t)(b*64 + (c&63)))*Ll + p0+px];
    }
    __syncthreads();
    int ot = tid % 32, pg = tid / 32;
    int o0 = ot*4, px0 = pg*7;
    int cnt = (px0 < PT) ? min(7, PT - px0) : 0;
    float acc[4][7];
    #pragma unroll
    for (int k=0;k<4;k++)
        #pragma unroll
        for (int j=0;j<7;j++) acc[k][j]=0.f;
    for (int c=0;c<256;c++){
        float w0=sw[(o0+0)*257+c], w1=sw[(o0+1)*257+c], w2=sw[(o0+2)*257+c], w3=sw[(o0+3)*257+c];
        #pragma unroll 7
        for (int j=0;j<7;j++){
            if (j<cnt){
                float xx = sx[c*PT + px0 + j];
                acc[0][j]+=w0*xx; acc[1][j]+=w1*xx; acc[2][j]+=w2*xx; acc[3][j]+=w3*xx;
            }
        }
    }
    #pragma unroll
    for (int k=0;k<4;k++)
        for (int j=0;j<cnt;j++){
            float v = bnf(acc[k][j], sbn, o0+k, 128);
            g_m1[((size_t)(b*128 + o0+k))*Ll + p0+px0+j] = fmaxf(v, 0.f);
        }
}

__global__ void __launch_bounds__(256,1)
k_mlp2_t(const float* __restrict__ x, const float* __restrict__ w,
         const float* __restrict__ bnp, float* __restrict__ out){
    extern __shared__ float sm[];
    float* sw = sm;
    float* sx = sw + 256*129;
    float* sbn = sx + 128*PT;
    int b = blockIdx.x / NTt, p0 = (blockIdx.x % NTt) * PT;
    int tid = threadIdx.x;
    for (int i=tid; i<256*128; i+=256){ sw[(i/128)*129 + (i%128)] = w[i]; }
    for (int i=tid; i<1024; i+=256) sbn[i] = bnp[i];
    for (int i=tid; i<128*PT; i+=256){
        int c=i/PT, px=i%PT;
        sx[i] = g_m1[((size_t)(b*128 + c))*Ll + p0+px];
    }
    __syncthreads();
    int og = tid % 64, pg = tid / 64;
    int o0 = og*4, px0 = pg*13;
    int cnt = min(13, PT - px0);
    float acc[4][13];
    #pragma unroll
    for (int k=0;k<4;k++)
        #pragma unroll
        for (int j=0;j<13;j++) acc[k][j]=0.f;
    for (int c=0;c<128;c++){
        float w0=sw[(o0+0)*129+c], w1=sw[(o0+1)*129+c], w2=sw[(o0+2)*129+c], w3=sw[(o0+3)*129+c];
        #pragma unroll 13
        for (int j=0;j<13;j++){
            if (j<cnt){
                float xx = sx[c*PT + px0 + j];
                acc[0][j]+=w0*xx; acc[1][j]+=w1*xx; acc[2][j]+=w2*xx; acc[3][j]+=w3*xx;
            }
        }
    }
    #pragma unroll
    for (int k=0;k<4;k++)
        for (int j=0;j<cnt;j++){
            size_t idx = ((size_t)(b*DIMc + o0+k))*Ll + p0+px0+j;
            out[idx] = x[idx] + bnf(acc[k][j], sbn, o0+k, 256);
        }
}

// ---------------- launch ----------------
extern "C" void kernel_launch(void* const* d_in, const int* in_sizes, int n_in,
                              void* d_out, int out_size){
    const float* x       = (const float*)d_in[0];
    const float* dw1_w   = (const float*)d_in[1];
    const float* dw1_b   = (const float*)d_in[2];
    const float* bn_dw1  = (const float*)d_in[3];
    const float* f1_w    = (const float*)d_in[4];
    const float* f1_b    = (const float*)d_in[5];
    const float* f2_w    = (const float*)d_in[6];
    const float* f2_b    = (const float*)d_in[7];
    const float* g_w     = (const float*)d_in[8];
    const float* g_b     = (const float*)d_in[9];
    const float* bn_g    = (const float*)d_in[10];
    const float* dw2_w   = (const float*)d_in[11];
    const float* dw2_b   = (const float*)d_in[12];
    const float* hatt1_w = (const float*)d_in[13];
    const float* vatt1_w = (const float*)d_in[14];
    const float* hatt2_w = (const float*)d_in[15];
    const float* vatt2_w = (const float*)d_in[16];
    const float* bn_mra  = (const float*)d_in[17];
    const float* bcdt_w  = (const float*)d_in[18];
    const float* ssd_dw_w= (const float*)d_in[19];
    const float* hz_w    = (const float*)d_in[20];
    const float* out_w   = (const float*)d_in[21];
    const float* A_param = (const float*)d_in[22];
    const float* D_param = (const float*)d_in[23];
    const float* qkv_w   = (const float*)d_in[24];
    const float* proj_w  = (const float*)d_in[25];
    const float* bn_n4   = (const float*)d_in[26];
    const float* mlp1_w  = (const float*)d_in[27];
    const float* bn_mlp  = (const float*)d_in[28];
    const float* mlp2_w  = (const float*)d_in[29];
    const float* bn_n1   = (const float*)d_in[30];
    float* out = (float*)d_out;
    (void)n_in; (void)in_sizes; (void)out_size;

    const int NE  = Bq*Cc*Ll;
    const int NE3 = Bq*192*Ll;
    const int TB  = Bq*NTt;

    const int SM_STAR = (8192*3 + 128 + 128 + 64 + 256 + 64*PT + 128*PT) * 4;
    const int SM_BCDT = (192*65 + 64*PT) * 4;
    const int SM_PROJ = (64*65 + 64*PT + 256) * 4;
    const int SM_MLP1 = (128*257 + 256*PT + 512) * 4;
    const int SM_MLP2 = (256*129 + 128*PT + 1024) * 4;

    cudaFuncSetAttribute(k_star_t, cudaFuncAttributeMaxDynamicSharedMemorySize, SM_STAR);
    cudaFuncSetAttribute(k_bcdt_t, cudaFuncAttributeMaxDynamicSharedMemorySize, SM_BCDT);
    cudaFuncSetAttribute(k_qkv_t,  cudaFuncAttributeMaxDynamicSharedMemorySize, SM_BCDT);
    cudaFuncSetAttribute(k_mlp1_t, cudaFuncAttributeMaxDynamicSharedMemorySize, SM_MLP1);
    cudaFuncSetAttribute(k_mlp2_t, cudaFuncAttributeMaxDynamicSharedMemorySize, SM_MLP2);

    // fork-join across 4 branches (capture-safe: fork from legacy stream via events)
    cudaStream_t s1, s2, s3;
    cudaStreamCreateWithFlags(&s1, cudaStreamNonBlocking);
    cudaStreamCreateWithFlags(&s2, cudaStreamNonBlocking);
    cudaStreamCreateWithFlags(&s3, cudaStreamNonBlocking);
    cudaEvent_t e0, e1, e2, e3;
    cudaEventCreateWithFlags(&e0, cudaEventDisableTiming);
    cudaEventCreateWithFlags(&e1, cudaEventDisableTiming);
    cudaEventCreateWithFlags(&e2, cudaEventDisableTiming);
    cudaEventCreateWithFlags(&e3, cudaEventDisableTiming);

    cudaEventRecord(e0, 0);
    cudaStreamWaitEvent(s1, e0, 0);
    cudaStreamWaitEvent(s2, e0, 0);
    cudaStreamWaitEvent(s3, e0, 0);

    // branch 1 on s1
    k_dw7a<<<(NE+255)/256, 256, 0, s1>>>(x, dw1_w, dw1_b, bn_dw1);
    k_star_t<<<TB, 256, SM_STAR, s1>>>(f1_w, f1_b, f2_w, f2_b, g_w, g_b, bn_g);
    k_dw7b<<<(NE+255)/256, 256, 0, s1>>>(dw2_w, dw2_b);

    // branch 2 on s2
    k_att2<<<Bq*Cc, 256, 0, s2>>>(x, hatt1_w, vatt1_w, hatt2_w, vatt2_w, bn_mra);

    // branch 4 on s3
    k_qkv_t<<<TB, 240, SM_BCDT, s3>>>(x, qkv_w);
    k_attn<<<Bq*NHh, Ll, 0, s3>>>();
    k_proj_t<<<TB, 256, SM_PROJ, s3>>>(x, proj_w, bn_n4);

    // branch 3 on legacy stream
    k_bcdt_t<<<TB, 240, SM_BCDT>>>(x, bcdt_w);
    k_dw3<<<(NE3+255)/256, 256>>>(ssd_dw_w);
    k_softAB<<<Bq*Sdim, 256>>>(A_param);
    k_hg<<<dim3(Bq, 2), 256>>>(x);
    k_hz<<<Bq*Sdim, 128>>>(hz_w, out_w, D_param);
    k_x3<<<dim3(Bq, 7), 256>>>();

    // join
    cudaEventRecord(e1, s1); cudaStreamWaitEvent(0, e1, 0);
    cudaEventRecord(e2, s2); cudaStreamWaitEvent(0, e2, 0);
    cudaEventRecord(e3, s3); cudaStreamWaitEvent(0, e3, 0);

    // merge MLP on legacy stream
    k_mlp1_t<<<TB, 256, SM_MLP1>>>(mlp1_w, bn_mlp);
    k_mlp2_t<<<TB, 256, SM_MLP2>>>(x, mlp2_w, bn_n1, out);

    cudaEventDestroy(e0); cudaEventDestroy(e1);
    cudaEventDestroy(e2); cudaEventDestroy(e3);
    cudaStreamDestroy(s1); cudaStreamDestroy(s2); cudaStreamDestroy(s3);
}